// round 2
// baseline (speedup 1.0000x reference)
#include <cuda_runtime.h>
#include <math.h>

// Problem constants (fixed shapes for this problem instance)
#define B_  4
#define C_  64
#define H_  282
#define W_  282
#define P_  12000
#define HW_ (H_ * W_)          // 79524

// Scratch (device globals — no allocation allowed in kernel_launch)
__device__ int g_winner[B_ * HW_];   // per (batch, cell): highest pillar index p writing there, -1 if none
__device__ int g_cell  [B_ * P_];    // per (batch, pillar): target cell, -1 if invalid

// ---------------------------------------------------------------------------
// Kernel 1: zero the output canvas (float4 vectorized) and reset winner array.
// n4 = total output floats / 4 (20,358,144 / 4 = 5,089,536) > B_*HW_ so the
// winner reset piggybacks on the same grid.
// ---------------------------------------------------------------------------
__global__ void k_zero(float4* __restrict__ out, int n4) {
    int i = blockIdx.x * blockDim.x + threadIdx.x;
    if (i < n4) {
        out[i] = make_float4(0.f, 0.f, 0.f, 0.f);
    }
    if (i < B_ * HW_) {
        g_winner[i] = -1;
    }
}

// ---------------------------------------------------------------------------
// Kernel 2: compute grid cell per (b, p); atomicMax the winner (sequential
// last-update-wins of XLA scatter == highest pillar index wins).
//
// Index math matches XLA's fast-math lowering of (x - (-22.0)) / 0.16:
// arcp rewrites the division into multiplication by the reciprocal, and
// float32(1 / float32(0.16)) rounds to EXACTLY 6.25f. Using a true IEEE
// division here flips floor() at cell boundaries (measured: 1 pillar flipped,
// rel_err 7.2e-3), so we must multiply by 6.25f.
// ---------------------------------------------------------------------------
__global__ void k_index(const float* __restrict__ pin) {
    int i = blockIdx.x * blockDim.x + threadIdx.x;   // i = b*P + p
    if (i >= B_ * P_) return;
    int b = i / P_;
    int p = i - b * P_;

    float x = pin[(b * 2 + 0) * P_ + p];
    float y = pin[(b * 2 + 1) * P_ + p];

    int cell = -1;
    if (x != 0.0f) {   // invalid pillars get OOB indices in the reference -> dropped by XLA scatter
        int xg = (int)floorf(__fmul_rn(__fadd_rn(x, 22.0f), 6.25f));
        int yg = (int)floorf(__fmul_rn(__fadd_rn(y, 22.0f), 6.25f));
        xg = min(max(xg, 0), W_ - 1);
        yg = min(max(yg, 0), H_ - 1);
        cell = yg * W_ + xg;
        atomicMax(&g_winner[b * HW_ + cell], p);
    }
    g_cell[i] = cell;
}

// ---------------------------------------------------------------------------
// Kernel 3: scatter features. Thread t = (b*C + c)*P + p, with p fastest so
// feature reads (B, C, P layout) are fully coalesced. Writes are inherently
// scattered (random cells) but hit L2 lines freshly zeroed by k_zero.
// Only the winning pillar per cell writes (matches serial last-wins scatter).
// ---------------------------------------------------------------------------
__global__ void k_scatter(const float* __restrict__ feats, float* __restrict__ out) {
    int t = blockIdx.x * blockDim.x + threadIdx.x;
    if (t >= B_ * C_ * P_) return;
    int bc = t / P_;          // b*C + c
    int p  = t - bc * P_;
    int b  = bc / C_;

    int cell = g_cell[b * P_ + p];
    if (cell < 0) return;
    if (g_winner[b * HW_ + cell] != p) return;

    out[bc * HW_ + cell] = feats[t];   // feats[(b*C+c)*P + p] == feats[t]
}

// ---------------------------------------------------------------------------
extern "C" void kernel_launch(void* const* d_in, const int* in_sizes, int n_in,
                              void* d_out, int out_size) {
    const float* pfn_input  = (const float*)d_in[0];   // (4, 2, 12000, 1)
    const float* pfn_output = (const float*)d_in[1];   // (4, 64, 12000)
    float* out = (float*)d_out;                        // (4, 64, 282, 282)

    const int n4 = (B_ * C_ * HW_) / 4;                // 5,089,536 float4s

    k_zero   <<<(n4 + 255) / 256,          256>>>((float4*)out, n4);
    k_index  <<<(B_ * P_ + 255) / 256,     256>>>(pfn_input);
    k_scatter<<<(B_ * C_ * P_ + 255) / 256, 256>>>(pfn_output, out);
}

// round 3
// speedup vs baseline: 1.4647x; 1.4647x over previous
#include <cuda_runtime.h>
#include <math.h>

// Problem constants (fixed shapes)
#define B_   4
#define C_   64
#define H_   282
#define W_   282
#define P_   12000
#define HW_  (H_ * W_)        // 79524
#define NQ_  (HW_ / 4)        // 19881 float4-quads per channel image

// Scratch (device global — no allocation allowed)
__device__ int g_winner[B_ * HW_];   // per (batch, cell): winning pillar index (max p), -1 if none

// ---------------------------------------------------------------------------
// Kernel 1: reset winner array to -1 (1.27 MB, trivial).
// ---------------------------------------------------------------------------
__global__ void k_reset() {
    int i = blockIdx.x * blockDim.x + threadIdx.x;
    if (i < B_ * HW_) g_winner[i] = -1;
}

// ---------------------------------------------------------------------------
// Kernel 2: per (b, p) compute target cell; atomicMax picks the highest
// pillar index per cell == sequential last-update-wins of XLA scatter.
// Index math must match XLA's fast-math lowering: (x + 22) * 6.25f
// (float32(1/0.16f) rounds to exactly 6.25f) — verified bit-exact in R2.
// Invalid pillars (x == 0) map OOB in the reference and are dropped.
// ---------------------------------------------------------------------------
__global__ void k_index(const float* __restrict__ pin) {
    int i = blockIdx.x * blockDim.x + threadIdx.x;   // i = b*P + p
    if (i >= B_ * P_) return;
    int b = i / P_;
    int p = i - b * P_;

    float x = pin[(b * 2 + 0) * P_ + p];
    if (x == 0.0f) return;
    float y = pin[(b * 2 + 1) * P_ + p];

    int xg = (int)floorf(__fmul_rn(__fadd_rn(x, 22.0f), 6.25f));
    int yg = (int)floorf(__fmul_rn(__fadd_rn(y, 22.0f), 6.25f));
    xg = min(max(xg, 0), W_ - 1);
    yg = min(max(yg, 0), H_ - 1);
    atomicMax(&g_winner[b * HW_ + yg * W_ + xg], p);
}

// ---------------------------------------------------------------------------
// Kernel 3: GATHER — single pass over the output. Each thread owns one
// (b, channel-group-of-16, x-quad): reads 4 winners as one int4 (coalesced),
// then for 16 channels gathers up to 4 features (L2-resident, 12.3 MB) and
// emits one float4 coalesced store per channel. Every output byte is written
// exactly once -> no separate zero pass, no scattered partial-sector stores.
// Threads: B*4*NQ = 318,096 (1243 blocks) -> ~8 blocks/SM, good occupancy.
// ---------------------------------------------------------------------------
__global__ void k_gather(const float* __restrict__ feats, float4* __restrict__ out) {
    int t = blockIdx.x * blockDim.x + threadIdx.x;
    if (t >= B_ * 4 * NQ_) return;
    int q4 = t % NQ_;            // x-quad within the (H,W) image
    int g  = t / NQ_;            // b*4 + cg
    int b  = g >> 2;
    int cg = g & 3;              // channel group (16 channels each)

    const int4* w4 = (const int4*)g_winner;     // B_*HW_ divisible by 4, aligned
    int4 w = w4[b * NQ_ + q4];

    const float* fb = feats + (size_t)b * C_ * P_ + (size_t)cg * 16 * P_;
    float4*      ob = out   + (size_t)(b * C_ + cg * 16) * NQ_ + q4;

    #pragma unroll
    for (int cc = 0; cc < 16; cc++) {
        const float* f = fb + cc * P_;
        float4 v;
        v.x = (w.x >= 0) ? __ldg(f + w.x) : 0.0f;
        v.y = (w.y >= 0) ? __ldg(f + w.y) : 0.0f;
        v.z = (w.z >= 0) ? __ldg(f + w.z) : 0.0f;
        v.w = (w.w >= 0) ? __ldg(f + w.w) : 0.0f;
        ob[(size_t)cc * NQ_] = v;
    }
}

// ---------------------------------------------------------------------------
extern "C" void kernel_launch(void* const* d_in, const int* in_sizes, int n_in,
                              void* d_out, int out_size) {
    const float* pfn_input  = (const float*)d_in[0];   // (4, 2, 12000, 1)
    const float* pfn_output = (const float*)d_in[1];   // (4, 64, 12000)
    float* out = (float*)d_out;                        // (4, 64, 282, 282)

    k_reset <<<(B_ * HW_ + 255) / 256, 256>>>();
    k_index <<<(B_ * P_  + 255) / 256, 256>>>(pfn_input);
    k_gather<<<(B_ * 4 * NQ_ + 255) / 256, 256>>>(pfn_output, (float4*)out);
}

// round 4
// speedup vs baseline: 1.5433x; 1.0537x over previous
#include <cuda_runtime.h>
#include <math.h>

// Problem constants (fixed shapes)
#define B_   4
#define C_   64
#define H_   282
#define W_   282
#define P_   12000
#define HW_  (H_ * W_)        // 79524
#define NQ_  (HW_ / 4)        // 19881 float4-quads per channel image

#define PT_  (P_ / 32)        // 375 pillar tiles (exact)
#define CT_  (C_ / 32)        // 2  channel tiles
#define TRANS_BLOCKS_ (B_ * PT_ * CT_)            // 3000
#define IDX_BLOCKS_   ((B_ * P_ + 255) / 256)     // 188

// Scratch (device globals; zero-initialized at module load — no resets needed)
__device__ __align__(16) int   g_winner[B_ * HW_];     // (p+1) of winning pillar, 0 = empty
__device__ __align__(16) float g_tf[B_ * P_ * C_];     // feats transposed to (B, P, C)

// ---------------------------------------------------------------------------
// Kernel 1 (fused): blocks [0, 3000) transpose feats (B,C,P) -> g_tf (B,P,C)
// via a 32x32 smem tile; blocks [3000, 3188) compute per-pillar cells and
// atomicMax(p+1) into g_winner (sequential last-update-wins == max p).
// Index math matches XLA fast-math lowering: (x + 22) * 6.25f (bit-verified).
// ---------------------------------------------------------------------------
__global__ void k_prep(const float* __restrict__ feats,
                       const float* __restrict__ pin) {
    if (blockIdx.x < TRANS_BLOCKS_) {
        // ---- transpose ----
        __shared__ float tile[32][33];
        int bid   = blockIdx.x;
        int b     = bid / (PT_ * CT_);
        int rem   = bid - b * (PT_ * CT_);
        int ctile = rem / PT_;            // 0..1
        int ptile = rem - ctile * PT_;    // 0..374
        int tx = threadIdx.x & 31;        // 0..31
        int ty = threadIdx.x >> 5;        // 0..7

        const float* src = feats + ((size_t)b * C_ + ctile * 32) * P_ + ptile * 32;
        #pragma unroll
        for (int i = 0; i < 4; i++) {
            int cl = ty + 8 * i;
            tile[cl][tx] = src[(size_t)cl * P_ + tx];     // coalesced in p
        }
        __syncthreads();
        float* dst = g_tf + ((size_t)b * P_ + ptile * 32) * C_ + ctile * 32;
        #pragma unroll
        for (int i = 0; i < 4; i++) {
            int pl = ty + 8 * i;
            dst[(size_t)pl * C_ + tx] = tile[tx][pl];     // coalesced in c
        }
    } else {
        // ---- index ----
        int i = (blockIdx.x - TRANS_BLOCKS_) * 256 + threadIdx.x;  // b*P + p
        if (i >= B_ * P_) return;
        int b = i / P_;
        int p = i - b * P_;

        float x = pin[(b * 2 + 0) * P_ + p];
        if (x == 0.0f) return;            // invalid pillars dropped (OOB in ref)
        float y = pin[(b * 2 + 1) * P_ + p];

        int xg = (int)floorf(__fmul_rn(__fadd_rn(x, 22.0f), 6.25f));
        int yg = (int)floorf(__fmul_rn(__fadd_rn(y, 22.0f), 6.25f));
        xg = min(max(xg, 0), W_ - 1);
        yg = min(max(yg, 0), H_ - 1);
        atomicMax(&g_winner[b * HW_ + yg * W_ + xg], p + 1);  // 0 = empty
    }
}

// ---------------------------------------------------------------------------
// Kernel 2: GATHER. One thread per (b, x-quad) owns ALL 64 channels:
//  - one int4 read of 4 winners (coalesced), immediately reset to 0 for the
//    next call (single owner per quad -> race-free self-reset),
//  - per group of 4 channels: one float4 load per non-empty lane from the
//    transposed features (pillar's 256B block stays L1-resident across the
//    loop), 4x4 register transpose, 4 coalesced float4 stores.
// 64 float4 stores/thread -> deep MLP on the store path. Every output byte
// written exactly once.
// ---------------------------------------------------------------------------
__global__ void k_gather(float4* __restrict__ out) {
    int t = blockIdx.x * blockDim.x + threadIdx.x;
    if (t >= B_ * NQ_) return;
    int b  = t / NQ_;
    int q4 = t - b * NQ_;

    int4* w4 = (int4*)g_winner;
    int4 w = w4[t];
    w4[t] = make_int4(0, 0, 0, 0);        // self-reset for next call

    const float* tb = g_tf + (size_t)b * P_ * C_;
    const float4* fx = (w.x > 0) ? (const float4*)(tb + (size_t)(w.x - 1) * C_) : nullptr;
    const float4* fy = (w.y > 0) ? (const float4*)(tb + (size_t)(w.y - 1) * C_) : nullptr;
    const float4* fz = (w.z > 0) ? (const float4*)(tb + (size_t)(w.z - 1) * C_) : nullptr;
    const float4* fw = (w.w > 0) ? (const float4*)(tb + (size_t)(w.w - 1) * C_) : nullptr;

    float4* ob = out + (size_t)b * C_ * NQ_ + q4;
    const float4 Z = make_float4(0.f, 0.f, 0.f, 0.f);

    #pragma unroll 4
    for (int gg = 0; gg < 16; gg++) {     // channel groups of 4
        float4 vx = fx ? __ldg(fx + gg) : Z;
        float4 vy = fy ? __ldg(fy + gg) : Z;
        float4 vz = fz ? __ldg(fz + gg) : Z;
        float4 vw = fw ? __ldg(fw + gg) : Z;

        ob[(size_t)(gg * 4 + 0) * NQ_] = make_float4(vx.x, vy.x, vz.x, vw.x);
        ob[(size_t)(gg * 4 + 1) * NQ_] = make_float4(vx.y, vy.y, vz.y, vw.y);
        ob[(size_t)(gg * 4 + 2) * NQ_] = make_float4(vx.z, vy.z, vz.z, vw.z);
        ob[(size_t)(gg * 4 + 3) * NQ_] = make_float4(vx.w, vy.w, vz.w, vw.w);
    }
}

// ---------------------------------------------------------------------------
extern "C" void kernel_launch(void* const* d_in, const int* in_sizes, int n_in,
                              void* d_out, int out_size) {
    const float* pfn_input  = (const float*)d_in[0];   // (4, 2, 12000, 1)
    const float* pfn_output = (const float*)d_in[1];   // (4, 64, 12000)
    float* out = (float*)d_out;                        // (4, 64, 282, 282)

    k_prep  <<<TRANS_BLOCKS_ + IDX_BLOCKS_, 256>>>(pfn_output, pfn_input);
    k_gather<<<(B_ * NQ_ + 255) / 256,      256>>>((float4*)out);
}

// round 5
// speedup vs baseline: 1.5450x; 1.0011x over previous
#include <cuda_runtime.h>
#include <math.h>

// Problem constants (fixed shapes)
#define B_   4
#define C_   64
#define H_   282
#define W_   282
#define P_   12000
#define HW_  (H_ * W_)        // 79524
#define NQ_  (HW_ / 4)        // 19881 float4-quads per channel image
#define QB_  32               // quads per gather block
#define QBLK_ ((NQ_ + QB_ - 1) / QB_)   // 622 quad-blocks per batch

#define PT_  (P_ / 32)        // 375 pillar tiles (exact)
#define CT_  (C_ / 32)        // 2  channel tiles
#define TRANS_BLOCKS_ (B_ * PT_ * CT_)            // 3000
#define IDX_BLOCKS_   ((B_ * P_ + 255) / 256)     // 188

// Scratch (device globals; zero-initialized at module load, and g_winner is
// self-resetting inside k_gather -> no reset kernel ever needed)
__device__ __align__(16) int   g_winner[B_ * HW_];     // (p+1) of winning pillar, 0 = empty
__device__ __align__(16) float g_tf[B_ * P_ * C_];     // feats transposed to (B, P, C)

// ---------------------------------------------------------------------------
// Kernel 1 (fused): blocks [0, 3000) transpose feats (B,C,P) -> g_tf (B,P,C)
// via a 32x32 smem tile; blocks [3000, 3188) compute per-pillar cells and
// atomicMax(p+1) into g_winner (sequential last-update-wins == max p).
// Index math matches XLA fast-math lowering: (x + 22) * 6.25f (bit-verified).
// ---------------------------------------------------------------------------
__global__ void k_prep(const float* __restrict__ feats,
                       const float* __restrict__ pin) {
    if (blockIdx.x < TRANS_BLOCKS_) {
        __shared__ float tile[32][33];
        int bid   = blockIdx.x;
        int b     = bid / (PT_ * CT_);
        int rem   = bid - b * (PT_ * CT_);
        int ctile = rem / PT_;            // 0..1
        int ptile = rem - ctile * PT_;    // 0..374
        int tx = threadIdx.x & 31;
        int ty = threadIdx.x >> 5;

        const float* src = feats + ((size_t)b * C_ + ctile * 32) * P_ + ptile * 32;
        #pragma unroll
        for (int i = 0; i < 4; i++) {
            int cl = ty + 8 * i;
            tile[cl][tx] = src[(size_t)cl * P_ + tx];     // coalesced in p
        }
        __syncthreads();
        float* dst = g_tf + ((size_t)b * P_ + ptile * 32) * C_ + ctile * 32;
        #pragma unroll
        for (int i = 0; i < 4; i++) {
            int pl = ty + 8 * i;
            dst[(size_t)pl * C_ + tx] = tile[tx][pl];     // coalesced in c
        }
    } else {
        int i = (blockIdx.x - TRANS_BLOCKS_) * 256 + threadIdx.x;  // b*P + p
        if (i >= B_ * P_) return;
        int b = i / P_;
        int p = i - b * P_;

        float x = pin[(b * 2 + 0) * P_ + p];
        if (x == 0.0f) return;            // invalid pillars dropped (OOB in ref)
        float y = pin[(b * 2 + 1) * P_ + p];

        int xg = (int)floorf(__fmul_rn(__fadd_rn(x, 22.0f), 6.25f));
        int yg = (int)floorf(__fmul_rn(__fadd_rn(y, 22.0f), 6.25f));
        xg = min(max(xg, 0), W_ - 1);
        yg = min(max(yg, 0), H_ - 1);
        atomicMax(&g_winner[b * HW_ + yg * W_ + xg], p + 1);  // 0 = empty
    }
}

// ---------------------------------------------------------------------------
// Kernel 2: GATHER. Block = (b, 32 quads); thread (q=tid&31, cg=tid>>5)
// handles 8 channels [cg*8, cg*8+8) of quad q.
//  Stage 1: 32 threads load the block's winner int4s into smem and zero them
//           (single owner per quad -> race-free self-reset for next call).
//  Stage 2: per winner lane, each cg thread reads its OWN 32B slice (2 x
//           float4) of the pillar's 256B transposed-feature block (no
//           cross-cg redundancy), register-transposes, and emits 8 coalesced
//           float4 stores (warp = one cg over 32 consecutive quads).
// Grid 2488 blocks (~17/SM) fixes the R4 occupancy ceiling (was 311 blocks).
// ---------------------------------------------------------------------------
__global__ void k_gather(float4* __restrict__ out) {
    __shared__ int4 w_s[QB_];

    int blk   = blockIdx.x;
    int b     = blk / QBLK_;
    int qblk  = blk - b * QBLK_;
    int qbase = qblk * QB_;                 // first quad of this block
    int nq    = min(QB_, NQ_ - qbase);      // quads in this block (last: 9)

    int tid = threadIdx.x;
    int q   = tid & 31;
    int cg  = tid >> 5;                     // 0..7

    int4* w4 = (int4*)g_winner;
    if (tid < nq) {
        int gi = b * NQ_ + qbase + tid;
        w_s[tid] = w4[gi];
        w4[gi] = make_int4(0, 0, 0, 0);     // self-reset
    }
    __syncthreads();
    if (q >= nq) return;

    int4 w = w_s[q];
    const float* tb = g_tf + (size_t)b * P_ * C_;
    const float4* fx = (w.x > 0) ? (const float4*)(tb + (size_t)(w.x - 1) * C_) + cg * 2 : nullptr;
    const float4* fy = (w.y > 0) ? (const float4*)(tb + (size_t)(w.y - 1) * C_) + cg * 2 : nullptr;
    const float4* fz = (w.z > 0) ? (const float4*)(tb + (size_t)(w.z - 1) * C_) + cg * 2 : nullptr;
    const float4* fw = (w.w > 0) ? (const float4*)(tb + (size_t)(w.w - 1) * C_) + cg * 2 : nullptr;

    const float4 Z = make_float4(0.f, 0.f, 0.f, 0.f);
    float4 vx0 = fx ? __ldg(fx)     : Z,  vx1 = fx ? __ldg(fx + 1) : Z;
    float4 vy0 = fy ? __ldg(fy)     : Z,  vy1 = fy ? __ldg(fy + 1) : Z;
    float4 vz0 = fz ? __ldg(fz)     : Z,  vz1 = fz ? __ldg(fz + 1) : Z;
    float4 vw0 = fw ? __ldg(fw)     : Z,  vw1 = fw ? __ldg(fw + 1) : Z;

    float4* ob = out + ((size_t)b * C_ + cg * 8) * NQ_ + qbase + q;
    ob[0 * (size_t)NQ_] = make_float4(vx0.x, vy0.x, vz0.x, vw0.x);
    ob[1 * (size_t)NQ_] = make_float4(vx0.y, vy0.y, vz0.y, vw0.y);
    ob[2 * (size_t)NQ_] = make_float4(vx0.z, vy0.z, vz0.z, vw0.z);
    ob[3 * (size_t)NQ_] = make_float4(vx0.w, vy0.w, vz0.w, vw0.w);
    ob[4 * (size_t)NQ_] = make_float4(vx1.x, vy1.x, vz1.x, vw1.x);
    ob[5 * (size_t)NQ_] = make_float4(vx1.y, vy1.y, vz1.y, vw1.y);
    ob[6 * (size_t)NQ_] = make_float4(vx1.z, vy1.z, vz1.z, vw1.z);
    ob[7 * (size_t)NQ_] = make_float4(vx1.w, vy1.w, vz1.w, vw1.w);
}

// ---------------------------------------------------------------------------
extern "C" void kernel_launch(void* const* d_in, const int* in_sizes, int n_in,
                              void* d_out, int out_size) {
    const float* pfn_input  = (const float*)d_in[0];   // (4, 2, 12000, 1)
    const float* pfn_output = (const float*)d_in[1];   // (4, 64, 12000)
    float* out = (float*)d_out;                        // (4, 64, 282, 282)

    k_prep  <<<TRANS_BLOCKS_ + IDX_BLOCKS_, 256>>>(pfn_output, pfn_input);
    k_gather<<<B_ * QBLK_,                  256>>>((float4*)out);
}